// round 1
// baseline (speedup 1.0000x reference)
#include <cuda_runtime.h>
#include <cuda_bf16.h>

// Sim2: temporal cost-volume + softmax + 1x1convs on a 3-level pyramid.
// All fp32. Stages:
//   k_sim      : partial cost volume L[cc][b,t,s,px] (smem-tiled, float4-over-c)
//   k_softconv1: reduce chunks + softmax(81) + conv1(243->4) + BN + SiLU
//   k_resize   : bilinear align_corners upsample of the 4-ch sim feature
//   k_conv2    : per-level (C+4)->C 1x1 conv + BN + SiLU  (SIMT GEMM 64x64x16)

#define B_   4
#define C2   512
#define HW2  400
#define NS_  81
#define NCHUNK 8
#define CCH  64

__device__ float g_Lpart[NCHUNK * 12 * NS_ * HW2];   // 12.4 MB scratch
__device__ float g_simf[B_ * 4 * HW2];
__device__ float g_pr0[B_ * 4 * 6400];
__device__ float g_pr1[B_ * 4 * 1600];

// ---------------------------------------------------------------------------
// Kernel 1: cost volume partials. grid = (NCHUNK, B*3), 512 threads.
// smem: curS[16][400] float4 (c-fastest), pastS[16][400] float4 -> 204.8 KB
// ---------------------------------------------------------------------------
__global__ __launch_bounds__(512) void k_sim(const float* __restrict__ f2)
{
    int cc = blockIdx.x;            // channel chunk 0..7
    int bt = blockIdx.y;            // 0..11  (b*3 + t)
    int b = bt / 3, t = bt - 3 * b;

    extern __shared__ float4 sh4[];
    float4* curS  = sh4;            // [16][400]
    float4* pastS = sh4 + 16 * HW2; // [16][400]

    const float* curG  = f2 + ((size_t)(b * 4 + 3) * C2 + cc * CCH) * HW2;
    const float* pastG = f2 + ((size_t)(b * 4 + t) * C2 + cc * CCH) * HW2;

    for (int idx = threadIdx.x; idx < 16 * HW2; idx += 512) {
        int c4 = idx / HW2, px = idx - c4 * HW2;
        int g = c4 * 4 * HW2 + px;
        curS[idx]  = make_float4(curG[g],  curG[g + HW2],  curG[g + 2 * HW2],  curG[g + 3 * HW2]);
        pastS[idx] = make_float4(pastG[g], pastG[g + HW2], pastG[g + 2 * HW2], pastG[g + 3 * HW2]);
    }
    __syncthreads();

    float* Lp = g_Lpart + ((size_t)cc * 12 + bt) * (NS_ * HW2);

    for (int i = threadIdx.x; i < NS_ * HW2; i += 512) {
        int s  = i / HW2, px = i - s * HW2;
        int y  = px / 20, x  = px - y * 20;
        int yy = y + s / 9 - 4;
        int xx = x + s % 9 - 4;

        float acc = 0.f;
        const float4* pp = pastS + px;
        if ((unsigned)yy < 20u && (unsigned)xx < 20u) {
            const float4* cp = curS + yy * 20 + xx;
#pragma unroll
            for (int c = 0; c < 16; c++) {
                float4 a = cp[c * HW2];
                float4 p = pp[c * HW2];
                acc -= fabsf(a.x - p.x); acc -= fabsf(a.y - p.y);
                acc -= fabsf(a.z - p.z); acc -= fabsf(a.w - p.w);
            }
        } else {
#pragma unroll
            for (int c = 0; c < 16; c++) {
                float4 p = pp[c * HW2];
                acc -= fabsf(p.x); acc -= fabsf(p.y);
                acc -= fabsf(p.z); acc -= fabsf(p.w);
            }
        }
        Lp[i] = acc;
    }
}

// ---------------------------------------------------------------------------
// Kernel 2: reduce 8 chunks, softmax over 81 displacements (per t),
// conv1 (3*81 -> 4) + BN + SiLU. grid = (4, B), 512 threads.
// threads = 128 px lanes x 4 groups. smem: Ls[243][128] + opart[12][128]
// ---------------------------------------------------------------------------
__global__ __launch_bounds__(512) void k_softconv1(
    const float* __restrict__ w1,
    const float* __restrict__ g1, const float* __restrict__ b1,
    const float* __restrict__ m1, const float* __restrict__ v1)
{
    int b    = blockIdx.y;
    int lane = threadIdx.x & 127;
    int grp  = threadIdx.x >> 7;
    int px   = blockIdx.x * 128 + lane;
    bool act = px < HW2;

    extern __shared__ float Ls[];           // [243][128]
    float* opart = Ls + 243 * 128;          // [12][128]

    const float* base = g_Lpart + (size_t)(b * 3) * NS_ * HW2;

    for (int ts = grp; ts < 243; ts += 4) {
        float vsum = 0.f;
        if (act) {
            size_t off = (size_t)ts * HW2 + px;
#pragma unroll
            for (int cc = 0; cc < NCHUNK; cc++)
                vsum += base[(size_t)cc * (12 * NS_ * HW2) + off];
        }
        Ls[ts * 128 + lane] = vsum;
    }
    __syncthreads();

    if (grp < 3) {
        int t = grp;
        float mx = -1e30f;
        for (int s = 0; s < 81; s++)
            mx = fmaxf(mx, Ls[(t * 81 + s) * 128 + lane]);
        float Z = 0.f;
        for (int s = 0; s < 81; s++)
            Z += __expf(Ls[(t * 81 + s) * 128 + lane] - mx);
        float rz = 1.f / Z;
        float o0 = 0, o1 = 0, o2 = 0, o3 = 0;
        for (int s = 0; s < 81; s++) {
            int k = t * 81 + s;
            float p = __expf(Ls[k * 128 + lane] - mx) * rz;
            o0 += w1[k] * p;       o1 += w1[243 + k] * p;
            o2 += w1[486 + k] * p; o3 += w1[729 + k] * p;
        }
        opart[(t * 4 + 0) * 128 + lane] = o0;
        opart[(t * 4 + 1) * 128 + lane] = o1;
        opart[(t * 4 + 2) * 128 + lane] = o2;
        opart[(t * 4 + 3) * 128 + lane] = o3;
    }
    __syncthreads();

    if (grp == 3 && act) {
#pragma unroll
        for (int oc = 0; oc < 4; oc++) {
            float o = opart[oc * 128 + lane] + opart[(4 + oc) * 128 + lane]
                    + opart[(8 + oc) * 128 + lane];
            float sc = g1[oc] * rsqrtf(v1[oc] + 1e-3f);
            float yv = (o - m1[oc]) * sc + b1[oc];
            g_simf[((size_t)b * 4 + oc) * HW2 + px] = yv / (1.f + __expf(-yv));
        }
    }
}

// ---------------------------------------------------------------------------
// Kernel 3: bilinear resize 20x20 -> Ho x Wo, align_corners=True
// ---------------------------------------------------------------------------
__global__ void k_resize(float* __restrict__ dst, int Ho, int Wo)
{
    int idx = blockIdx.x * 256 + threadIdx.x;
    int total = B_ * 4 * Ho * Wo;
    if (idx >= total) return;
    int xo = idx % Wo;
    int r  = idx / Wo;
    int yo = r % Ho;
    int bc = r / Ho;                         // b*4 + ch

    float cy = yo * (19.f / (float)(Ho - 1));
    float cx = xo * (19.f / (float)(Wo - 1));
    int y0 = (int)floorf(cy), x0 = (int)floorf(cx);
    int y1 = min(y0 + 1, 19), x1 = min(x0 + 1, 19);
    float wy = cy - (float)y0, wx = cx - (float)x0;

    const float* sp = g_simf + (size_t)bc * HW2;
    float v = (1.f - wy) * ((1.f - wx) * sp[y0 * 20 + x0] + wx * sp[y0 * 20 + x1])
            +         wy * ((1.f - wx) * sp[y1 * 20 + x0] + wx * sp[y1 * 20 + x1]);
    dst[idx] = v;
}

// ---------------------------------------------------------------------------
// Kernel 4: per-level 1x1 conv (C+4 -> C) + BN + SiLU.
// SIMT GEMM: block tile 64(o) x 64(px), K-chunk 16, 256 threads, 4x4 microtile.
// grid = (ceil(HW/64), C/64, B)
// ---------------------------------------------------------------------------
__global__ __launch_bounds__(256) void k_conv2(
    const float* __restrict__ feat,   // [B][4][C][HW], frame 3 used
    const float* __restrict__ pr,     // [B][4][HW]
    const float* __restrict__ w2,     // [C][C+4]
    const float* __restrict__ gg, const float* __restrict__ bb,
    const float* __restrict__ mm, const float* __restrict__ vv,
    float* __restrict__ out,          // [B][C][HW]
    int C, int HW)
{
    __shared__ float wsT[16][68];     // [k][o]
    __shared__ float xs[16][68];      // [k][px]

    int b     = blockIdx.z;
    int otile = blockIdx.y * 64;
    int ptile = blockIdx.x * 64;
    int K     = C + 4;

    const float* xbase = feat + (size_t)(b * 4 + 3) * C * HW;
    const float* prb   = pr + (size_t)b * 4 * HW;

    int tx = threadIdx.x & 15;
    int ty = threadIdx.x >> 4;

    float acc[4][4] = {};

    for (int k0 = 0; k0 < K; k0 += 16) {
        for (int i = threadIdx.x; i < 1024; i += 256) {
            int k = i & 15, o = i >> 4;
            int kk = k0 + k;
            wsT[k][o] = (kk < K) ? w2[(size_t)(otile + o) * K + kk] : 0.f;
        }
        for (int i = threadIdx.x; i < 1024; i += 256) {
            int px = i & 63, k = i >> 6;
            int kk = k0 + k, pp = ptile + px;
            float val = 0.f;
            if (kk < K && pp < HW)
                val = (kk < C) ? xbase[(size_t)kk * HW + pp]
                               : prb[(size_t)(kk - C) * HW + pp];
            xs[k][px] = val;
        }
        __syncthreads();
#pragma unroll
        for (int k = 0; k < 16; k++) {
            float4 a  = *(const float4*)&wsT[k][ty * 4];
            float4 xv = *(const float4*)&xs[k][tx * 4];
            acc[0][0] += a.x * xv.x; acc[0][1] += a.x * xv.y; acc[0][2] += a.x * xv.z; acc[0][3] += a.x * xv.w;
            acc[1][0] += a.y * xv.x; acc[1][1] += a.y * xv.y; acc[1][2] += a.y * xv.z; acc[1][3] += a.y * xv.w;
            acc[2][0] += a.z * xv.x; acc[2][1] += a.z * xv.y; acc[2][2] += a.z * xv.z; acc[2][3] += a.z * xv.w;
            acc[3][0] += a.w * xv.x; acc[3][1] += a.w * xv.y; acc[3][2] += a.w * xv.z; acc[3][3] += a.w * xv.w;
        }
        __syncthreads();
    }

#pragma unroll
    for (int i = 0; i < 4; i++) {
        int oo = otile + ty * 4 + i;          // C is a multiple of 64 -> always valid
        float sc = gg[oo] * rsqrtf(vv[oo] + 1e-3f);
        float sh = bb[oo] - mm[oo] * sc;
        int pp0 = ptile + tx * 4;
        float4 r;
        float* rp = &r.x;
#pragma unroll
        for (int j = 0; j < 4; j++) {
            float yv = acc[i][j] * sc + sh;
            rp[j] = yv / (1.f + __expf(-yv));
        }
        float* ob = out + (size_t)(b * C + oo) * HW;
        if (pp0 + 3 < HW) {
            *(float4*)(ob + pp0) = r;
        } else {
#pragma unroll
            for (int j = 0; j < 4; j++)
                if (pp0 + j < HW) ob[pp0 + j] = rp[j];
        }
    }
}

// ---------------------------------------------------------------------------
// Launch
// ---------------------------------------------------------------------------
extern "C" void kernel_launch(void* const* d_in, const int* in_sizes, int n_in,
                              void* d_out, int out_size)
{
    const float *f0 = nullptr, *f1 = nullptr, *f2 = nullptr, *w1 = nullptr;
    const float* bn1[4] = {nullptr, nullptr, nullptr, nullptr};
    const float* w2[3]  = {nullptr, nullptr, nullptr};
    const float* bn2[3][4];

    for (int i = 0; i < n_in; i++) {
        int sz = in_sizes[i];
        if (sz == 13107200)      f0 = (const float*)d_in[i];
        else if (sz == 6553600)  f1 = (const float*)d_in[i];
        else if (sz == 3276800)  f2 = (const float*)d_in[i];
        else if (sz == 972) {
            w1 = (const float*)d_in[i];
            for (int j = 0; j < 4; j++) bn1[j] = (const float*)d_in[i + 1 + j];
        } else if (sz == 16896) {
            w2[0] = (const float*)d_in[i];
            for (int j = 0; j < 4; j++) bn2[0][j] = (const float*)d_in[i + 1 + j];
        } else if (sz == 66560) {
            w2[1] = (const float*)d_in[i];
            for (int j = 0; j < 4; j++) bn2[1][j] = (const float*)d_in[i + 1 + j];
        } else if (sz == 264192) {
            w2[2] = (const float*)d_in[i];
            for (int j = 0; j < 4; j++) bn2[2][j] = (const float*)d_in[i + 1 + j];
        }
        // sizes 16 / 4 outside the bn groups = clip ids (unused by the math)
    }
    if (!f0 || !f1 || !f2 || !w1 || !w2[0] || !w2[1] || !w2[2]) return;

    cudaFuncSetAttribute(k_sim, cudaFuncAttributeMaxDynamicSharedMemorySize, 2 * 16 * HW2 * 16);
    cudaFuncSetAttribute(k_softconv1, cudaFuncAttributeMaxDynamicSharedMemorySize,
                         (243 * 128 + 12 * 128) * (int)sizeof(float));

    void *pr0, *pr1;
    cudaGetSymbolAddress(&pr0, g_pr0);
    cudaGetSymbolAddress(&pr1, g_pr1);
    void* simf;
    cudaGetSymbolAddress(&simf, g_simf);

    float* out0 = (float*)d_out;
    float* out1 = out0 + (size_t)B_ * 128 * 6400;
    float* out2 = out1 + (size_t)B_ * 256 * 1600;

    k_sim<<<dim3(NCHUNK, 12), 512, 2 * 16 * HW2 * 16>>>(f2);
    k_softconv1<<<dim3(4, B_), 512, (243 * 128 + 12 * 128) * sizeof(float)>>>(
        w1, bn1[0], bn1[1], bn1[2], bn1[3]);
    k_resize<<<(B_ * 4 * 6400 + 255) / 256, 256>>>((float*)pr0, 80, 80);
    k_resize<<<(B_ * 4 * 1600 + 255) / 256, 256>>>((float*)pr1, 40, 40);

    k_conv2<<<dim3(100, 2, B_), 256>>>(f0, (const float*)pr0, w2[0],
        bn2[0][0], bn2[0][1], bn2[0][2], bn2[0][3], out0, 128, 6400);
    k_conv2<<<dim3(25, 4, B_), 256>>>(f1, (const float*)pr1, w2[1],
        bn2[1][0], bn2[1][1], bn2[1][2], bn2[1][3], out1, 256, 1600);
    k_conv2<<<dim3(7, 8, B_), 256>>>(f2, (const float*)simf, w2[2],
        bn2[2][0], bn2[2][1], bn2[2][2], bn2[2][3], out2, 512, 400);
}